// round 10
// baseline (speedup 1.0000x reference)
#include <cuda_runtime.h>
#include <cuda_bf16.h>
#include <cuda_fp16.h>
#include <math.h>
#include <stdint.h>

#define T_TOK   8192
#define D_DIM   1024
#define E_EXP   8
#define H_DIM   4096
#define BM      256
#define MAX_TILES (2 * T_TOK / BM + E_EXP)     // 72
#define MAX_SLOTS (MAX_TILES * BM)             // 18432

// ---------------- scratch (static device globals) --------------------------
__device__ int   g_counts[E_EXP];
__device__ int   g_cursor[E_EXP];
__device__ int   g_offp[E_EXP + 1];
__device__ int   g_tile_expert[MAX_TILES];
__device__ int   g_tok[MAX_SLOTS];
__device__ int   g_slotof[T_TOK * 2];
__device__ int   g_topi[T_TOK * 2];
__device__ float g_topw[T_TOK * 2];

// fp16 weights, transposed to [E][N][K] (K contiguous)
__device__ __half g_w1[(size_t)E_EXP * H_DIM * D_DIM];
__device__ __half g_w2[(size_t)E_EXP * D_DIM * H_DIM];
// fp16 activations
__device__ __half g_x16[(size_t)T_TOK * D_DIM];
__device__ __half g_h16[(size_t)MAX_SLOTS * H_DIM];
__device__ float  g_y[(size_t)MAX_SLOTS * D_DIM];

// ---------------- helpers --------------------------------------------------
__device__ __forceinline__ uint32_t s2u(const void* p) {
    uint32_t a;
    asm("{ .reg .u64 t; cvta.to.shared.u64 t, %1; cvt.u32.u64 %0, t; }"
        : "=r"(a) : "l"(p));
    return a;
}
__device__ __forceinline__ void cpa16(uint32_t dst, const void* src) {
    asm volatile("cp.async.cg.shared.global [%0], [%1], 16;"
                 :: "r"(dst), "l"(src) : "memory");
}
#define CP_COMMIT()  asm volatile("cp.async.commit_group;" ::: "memory")
#define CP_WAITG(n)  asm volatile("cp.async.wait_group %0;" :: "n"(n) : "memory")

#define LDSM4(r0, r1, r2, r3, addr)                                         \
    asm volatile("ldmatrix.sync.aligned.m8n8.x4.shared.b16 {%0,%1,%2,%3},[%4];" \
                 : "=r"(r0), "=r"(r1), "=r"(r2), "=r"(r3) : "r"(addr))

__device__ __forceinline__ void mma16816(float* c, const uint32_t* a,
                                         const uint32_t* b) {
    asm volatile(
        "mma.sync.aligned.m16n8k16.row.col.f32.f16.f16.f32 "
        "{%0,%1,%2,%3},{%4,%5,%6,%7},{%8,%9},{%0,%1,%2,%3};"
        : "+f"(c[0]), "+f"(c[1]), "+f"(c[2]), "+f"(c[3])
        : "r"(a[0]), "r"(a[1]), "r"(a[2]), "r"(a[3]), "r"(b[0]), "r"(b[1]));
}

// smem: 3 stages x 48KB (A 32K | B 16K), then bias, then token idx
#define OFF_A    0
#define OFF_B    32768
#define STAGE_B  49152
#define OFF_BIAS 147456
#define OFF_TOK  147968
#define SMEM_REQ (148992 + 256)

// ---------------- init -----------------------------------------------------
__global__ void init_kernel() {
    int i = blockIdx.x * blockDim.x + threadIdx.x;
    if (i < E_EXP) { g_counts[i] = 0; g_cursor[i] = 0; }
    if (i < MAX_SLOTS) g_tok[i] = -1;
}

// ---------------- router ---------------------------------------------------
__global__ void router_kernel(const float* __restrict__ x,
                              const float* __restrict__ Wg,
                              const float* __restrict__ bg) {
    int t    = (blockIdx.x * blockDim.x + threadIdx.x) >> 5;
    int lane = threadIdx.x & 31;
    if (t >= T_TOK) return;
    const float* xr = x + (size_t)t * D_DIM;

    float acc[E_EXP];
#pragma unroll
    for (int e = 0; e < E_EXP; e++) acc[e] = 0.f;
    for (int d = lane; d < D_DIM; d += 32) {
        float xv = xr[d];
        const float4* w = reinterpret_cast<const float4*>(Wg + (size_t)d * E_EXP);
        float4 wa = w[0], wb = w[1];
        acc[0] = fmaf(xv, wa.x, acc[0]); acc[1] = fmaf(xv, wa.y, acc[1]);
        acc[2] = fmaf(xv, wa.z, acc[2]); acc[3] = fmaf(xv, wa.w, acc[3]);
        acc[4] = fmaf(xv, wb.x, acc[4]); acc[5] = fmaf(xv, wb.y, acc[5]);
        acc[6] = fmaf(xv, wb.z, acc[6]); acc[7] = fmaf(xv, wb.w, acc[7]);
    }
#pragma unroll
    for (int e = 0; e < E_EXP; e++)
#pragma unroll
        for (int off = 16; off; off >>= 1)
            acc[e] += __shfl_xor_sync(0xffffffffu, acc[e], off);

    if (lane == 0) {
        float l[E_EXP];
#pragma unroll
        for (int e = 0; e < E_EXP; e++) l[e] = acc[e] + bg[e];
        float m = l[0];
#pragma unroll
        for (int e = 1; e < E_EXP; e++) m = fmaxf(m, l[e]);
        float s = 0.f;
#pragma unroll
        for (int e = 0; e < E_EXP; e++) { l[e] = expf(l[e] - m); s += l[e]; }
        float inv = 1.f / s;
        int i0 = 0;
#pragma unroll
        for (int e = 1; e < E_EXP; e++) if (l[e] > l[i0]) i0 = e;
        int i1 = (i0 == 0) ? 1 : 0;
#pragma unroll
        for (int e = 0; e < E_EXP; e++)
            if (e != i0 && l[e] > l[i1]) i1 = e;
        g_topi[2 * t + 0] = i0;  g_topw[2 * t + 0] = l[i0] * inv;
        g_topi[2 * t + 1] = i1;  g_topw[2 * t + 1] = l[i1] * inv;
        atomicAdd(&g_counts[i0], 1);
        atomicAdd(&g_counts[i1], 1);
    }
}

// ---------------- scan -----------------------------------------------------
__global__ void scan_kernel() {
    if (threadIdx.x == 0) {
        int o = 0;
        for (int e = 0; e < E_EXP; e++) {
            g_offp[e] = o;
            o += ((g_counts[e] + BM - 1) / BM) * BM;
        }
        g_offp[E_EXP] = o;
    }
    __syncthreads();
    for (int m = threadIdx.x; m < MAX_TILES; m += blockDim.x) {
        int s = m * BM, e = -1;
        for (int i = 0; i < E_EXP; i++)
            if (s >= g_offp[i] && s < g_offp[i + 1]) e = i;
        g_tile_expert[m] = e;
    }
}

// ---------------- scatter --------------------------------------------------
__global__ void scatter_kernel() {
    int t = blockIdx.x * blockDim.x + threadIdx.x;
    if (t >= T_TOK) return;
#pragma unroll
    for (int k = 0; k < 2; k++) {
        int e    = g_topi[2 * t + k];
        int pos  = atomicAdd(&g_cursor[e], 1);
        int slot = g_offp[e] + pos;
        g_tok[slot] = t;
        g_slotof[2 * t + k] = slot;
    }
}

// ---------------- weight transpose + fp16 convert --------------------------
__global__ void wsplit_kernel(const float* __restrict__ W1,
                              const float* __restrict__ W2) {
    __shared__ float t[32][33];
    int b = blockIdx.x;
    const float* W; __half* oh; int K, N, e, nt, kt;
    if (b < 32768) {
        W = W1; oh = g_w1; K = D_DIM; N = H_DIM;
        e = b >> 12; int r = b & 4095; nt = r & 127; kt = r >> 7;
    } else {
        int b2 = b - 32768;
        W = W2; oh = g_w2; K = H_DIM; N = D_DIM;
        e = b2 >> 12; int r = b2 & 4095; nt = r & 31; kt = r >> 5;
    }
    int n0 = nt * 32, k0 = kt * 32;
    int tx = threadIdx.x, ty = threadIdx.y;
    const float* We = W + (size_t)e * K * N;
#pragma unroll
    for (int i = 0; i < 32; i += 8)
        t[ty + i][tx] = We[(size_t)(k0 + ty + i) * N + n0 + tx];
    __syncthreads();
    __half* ohe = oh + (size_t)e * K * N;
#pragma unroll
    for (int i = 0; i < 32; i += 8) {
        float v = t[tx][ty + i];
        ohe[(size_t)(n0 + ty + i) * K + (k0 + tx)] = __float2half_rn(v);
    }
}

// ---------------- x fp16 convert -------------------------------------------
__global__ void xsplit_kernel(const float* __restrict__ x) {
    int i = blockIdx.x * blockDim.x + threadIdx.x;     // over T*D/4
    float4 v = reinterpret_cast<const float4*>(x)[i];
    __half2 p0 = __floats2half2_rn(v.x, v.y);
    __half2 p1 = __floats2half2_rn(v.z, v.w);
    uint2 o;
    o.x = *(uint32_t*)&p0;
    o.y = *(uint32_t*)&p1;
    reinterpret_cast<uint2*>(g_x16)[i] = o;
}

// ---------------- HMMA GEMM (256x128 tile, warp 64x64, k-chunk 64) ---------
// PHASE 1: h = gelu( gather(x16) @ W1[e]^T + b1 ) -> g_h16
// PHASE 2: y =        h16        @ W2[e]^T + b2   -> g_y
// 256 thr, 8 warps (4m x 2n), 3-stage cp.async ring, 2-deep prefetch.
template <int PHASE>
__global__ void __launch_bounds__(256, 1) gemm_mma(const float* __restrict__ bias) {
    constexpr int K  = (PHASE == 1) ? D_DIM : H_DIM;
    constexpr int N  = (PHASE == 1) ? H_DIM : D_DIM;
    constexpr int NC = K / 64;

    int mt_blk = blockIdx.y;
    int e = g_tile_expert[mt_blk];
    if (e < 0) return;
    int m0 = mt_blk * BM, n0 = blockIdx.x * 128;

    extern __shared__ char dyn_smem[];
    char* sm = (char*)(((uintptr_t)dyn_smem + 127) & ~(uintptr_t)127);
    uint32_t sb = s2u(sm);

    int tid  = threadIdx.x;
    int lane = tid & 31, wid = tid >> 5;
    int wm = wid >> 1, wn = wid & 1;         // 4m x 2n warp grid

    float* bias_s = (float*)(sm + OFF_BIAS);
    int*   tok_s  = (int*)(sm + OFF_TOK);

    if (tid < 128)
        bias_s[tid] = bias[(size_t)e * N + n0 + tid];
    {   // 256 rows of token indices (one per thread)
        if (PHASE == 1) {
            int tk = g_tok[m0 + tid];
            tok_s[tid] = (tk < 0) ? 0 : tk;
        } else {
            tok_s[tid] = m0 + tid;
        }
    }
    __syncthreads();

    const __half* A_g = (PHASE == 1) ? g_x16 : g_h16;
    const __half* B_g = ((PHASE == 1) ? g_w1 : g_w2) + ((size_t)e * N + n0) * K;

    // ldmatrix lane rows (128B rows, chunk ^ (row&7) swizzle)
    int q = lane >> 3, r = lane & 7;
    int rowA_[4], rowB_[4];
#pragma unroll
    for (int mt = 0; mt < 4; mt++)
        rowA_[mt] = wm * 64 + mt * 16 + (q & 1) * 8 + r;
#pragma unroll
    for (int j = 0; j < 4; j++)
        rowB_[j] = wn * 64 + j * 16 + (q >> 1) * 8 + r;
    int qhA = q >> 1;     // k-chunk select bit for A fragments
    int qhB = q & 1;      // k-chunk select bit for B fragments

    float acc[4][8][4];
#pragma unroll
    for (int a = 0; a < 4; a++)
#pragma unroll
        for (int b = 0; b < 8; b++)
#pragma unroll
            for (int c = 0; c < 4; c++) acc[a][b][c] = 0.f;

    // stage loader: A 8 x 16B (256 rows), B 4 x 16B (128 rows); rows = 128B
    auto load_stage = [&](int c) {
        if (c < NC) {
            int k0 = c * 64;
            uint32_t sbs = sb + (uint32_t)(c % 3) * STAGE_B;
#pragma unroll
            for (int i = 0; i < 8; i++) {
                int t = tid + i * 256;
                int row = t >> 3, chunk = t & 7;
                uint32_t soff = (uint32_t)row * 128 +
                                (((uint32_t)(chunk ^ (row & 7))) << 4);
                cpa16(sbs + OFF_A + soff,
                      A_g + (size_t)tok_s[row] * K + k0 + chunk * 8);
            }
#pragma unroll
            for (int i = 0; i < 4; i++) {
                int t = tid + i * 256;
                int row = t >> 3, chunk = t & 7;
                uint32_t soff = (uint32_t)row * 128 +
                                (((uint32_t)(chunk ^ (row & 7))) << 4);
                cpa16(sbs + OFF_B + soff,
                      B_g + (size_t)row * K + k0 + chunk * 8);
            }
        }
        CP_COMMIT();
    };

    load_stage(0);
    load_stage(1);

    for (int c = 0; c < NC; ++c) {
        CP_WAITG(1);
        __syncthreads();
        load_stage(c + 2);                 // 2-deep prefetch into free ring slot
        uint32_t sbs = sb + (uint32_t)(c % 3) * STAGE_B;
#pragma unroll
        for (int slice = 0; slice < 4; slice++) {
            uint32_t ah[4][4];
#pragma unroll
            for (int mt = 0; mt < 4; mt++) {
                int row = rowA_[mt];
                uint32_t off = (uint32_t)row * 128 +
                    (((uint32_t)((slice * 2 + qhA) ^ (row & 7))) << 4);
                LDSM4(ah[mt][0], ah[mt][1], ah[mt][2], ah[mt][3],
                      sbs + OFF_A + off);
            }
#pragma unroll
            for (int j = 0; j < 4; j++) {
                int row = rowB_[j];
                uint32_t off = (uint32_t)row * 128 +
                    (((uint32_t)((slice * 2 + qhB) ^ (row & 7))) << 4);
                uint32_t bh[4];
                LDSM4(bh[0], bh[1], bh[2], bh[3], sbs + OFF_B + off);
#pragma unroll
                for (int mt = 0; mt < 4; mt++) {
#pragma unroll
                    for (int jj = 0; jj < 2; jj++)
                        mma16816(acc[mt][j * 2 + jj], ah[mt], bh + jj * 2);
                }
            }
        }
    }

    // ---------------- epilogue (registers -> global) ----------------
    int g = lane >> 2, tc = lane & 3;
#pragma unroll
    for (int mt = 0; mt < 4; mt++) {
        int rowb = m0 + wm * 64 + mt * 16 + g;
#pragma unroll
        for (int h = 0; h < 2; h++) {
            int row = rowb + h * 8;
            size_t base = (size_t)row * N + n0 + wn * 64 + tc * 2;
#pragma unroll
            for (int nt = 0; nt < 8; nt++) {
                int nb = wn * 64 + nt * 8 + tc * 2;
                float u0 = acc[mt][nt][h * 2 + 0] + bias_s[nb];
                float u1 = acc[mt][nt][h * 2 + 1] + bias_s[nb + 1];
                if (PHASE == 1) {
                    u0 = 0.5f * u0 * (1.0f + erff(u0 * 0.7071067811865476f));
                    u1 = 0.5f * u1 * (1.0f + erff(u1 * 0.7071067811865476f));
                    __half2 p = __floats2half2_rn(u0, u1);
                    *(uint32_t*)(g_h16 + base + nt * 8) = *(uint32_t*)&p;
                } else {
                    float2 v = make_float2(u0, u1);
                    *(float2*)(g_y + base + nt * 8) = v;
                }
            }
        }
    }
}

// ---------------- combine --------------------------------------------------
__global__ void combine_kernel(float* __restrict__ out) {
    int i = blockIdx.x * blockDim.x + threadIdx.x;
    constexpr int Q = D_DIM / 4;
    if (i >= T_TOK * Q) return;
    int t = i / Q, qq = i - t * Q;
    int s0 = g_slotof[2 * t + 0], s1 = g_slotof[2 * t + 1];
    float w0 = g_topw[2 * t + 0], w1 = g_topw[2 * t + 1];
    const float4* y4 = reinterpret_cast<const float4*>(g_y);
    float4 a = y4[(size_t)s0 * Q + qq];
    float4 b = y4[(size_t)s1 * Q + qq];
    reinterpret_cast<float4*>(out)[i] =
        make_float4(fmaf(w0, a.x, w1 * b.x), fmaf(w0, a.y, w1 * b.y),
                    fmaf(w0, a.z, w1 * b.z), fmaf(w0, a.w, w1 * b.w));
}

// ---------------- launch ---------------------------------------------------
extern "C" void kernel_launch(void* const* d_in, const int* in_sizes, int n_in,
                              void* d_out, int out_size) {
    const float* x  = (const float*)d_in[0];
    const float* Wg = (const float*)d_in[1];
    const float* bg = (const float*)d_in[2];
    const float* W1 = (const float*)d_in[3];
    const float* b1 = (const float*)d_in[4];
    const float* W2 = (const float*)d_in[5];
    const float* b2 = (const float*)d_in[6];
    float* out = (float*)d_out;

    cudaFuncSetAttribute(gemm_mma<1>, cudaFuncAttributeMaxDynamicSharedMemorySize, SMEM_REQ);
    cudaFuncSetAttribute(gemm_mma<2>, cudaFuncAttributeMaxDynamicSharedMemorySize, SMEM_REQ);

    init_kernel<<<(MAX_SLOTS + 255) / 256, 256>>>();
    router_kernel<<<T_TOK / 8, 256>>>(x, Wg, bg);
    scan_kernel<<<1, 256>>>();
    scatter_kernel<<<T_TOK / 256, 256>>>();
    wsplit_kernel<<<65536, dim3(32, 8)>>>(W1, W2);
    xsplit_kernel<<<T_TOK * D_DIM / 4 / 256, 256>>>(x);
    gemm_mma<1><<<dim3(H_DIM / 128, MAX_TILES), 256, SMEM_REQ>>>(b1);
    gemm_mma<2><<<dim3(D_DIM / 128, MAX_TILES), 256, SMEM_REQ>>>(b2);
    combine_kernel<<<(T_TOK * (D_DIM / 4) + 255) / 256, 256>>>(out);
}

// round 11
// speedup vs baseline: 1.2127x; 1.2127x over previous
#include <cuda_runtime.h>
#include <cuda_bf16.h>
#include <cuda_fp16.h>
#include <math.h>
#include <stdint.h>

#define T_TOK   8192
#define D_DIM   1024
#define E_EXP   8
#define H_DIM   4096
#define BM      128
#define MAX_TILES (2 * T_TOK / BM + E_EXP)     // 136
#define MAX_SLOTS (MAX_TILES * BM)             // 17408

// ---------------- scratch (static device globals) --------------------------
__device__ int   g_counts[E_EXP];
__device__ int   g_cursor[E_EXP];
__device__ int   g_offp[E_EXP + 1];
__device__ int   g_tile_expert[MAX_TILES];
__device__ int   g_tok[MAX_SLOTS];
__device__ int   g_slotof[T_TOK * 2];
__device__ int   g_topi[T_TOK * 2];
__device__ float g_topw[T_TOK * 2];

// fp16 weights, transposed to [E][N][K] (K contiguous)
__device__ __half g_w1[(size_t)E_EXP * H_DIM * D_DIM];
__device__ __half g_w2[(size_t)E_EXP * D_DIM * H_DIM];
// fp16 activations
__device__ __half g_x16[(size_t)T_TOK * D_DIM];
__device__ __half g_h16[(size_t)MAX_SLOTS * H_DIM];
__device__ float  g_y[(size_t)MAX_SLOTS * D_DIM];

// ---------------- helpers --------------------------------------------------
__device__ __forceinline__ uint32_t s2u(const void* p) {
    uint32_t a;
    asm("{ .reg .u64 t; cvta.to.shared.u64 t, %1; cvt.u32.u64 %0, t; }"
        : "=r"(a) : "l"(p));
    return a;
}
__device__ __forceinline__ void cpa16(uint32_t dst, const void* src) {
    asm volatile("cp.async.cg.shared.global [%0], [%1], 16;"
                 :: "r"(dst), "l"(src) : "memory");
}
#define CP_COMMIT()  asm volatile("cp.async.commit_group;" ::: "memory")
#define CP_WAITG(n)  asm volatile("cp.async.wait_group %0;" :: "n"(n) : "memory")

#define LDSM4(r0, r1, r2, r3, addr)                                         \
    asm volatile("ldmatrix.sync.aligned.m8n8.x4.shared.b16 {%0,%1,%2,%3},[%4];" \
                 : "=r"(r0), "=r"(r1), "=r"(r2), "=r"(r3) : "r"(addr))

__device__ __forceinline__ void mma16816(float* c, const uint32_t* a,
                                         const uint32_t* b) {
    asm volatile(
        "mma.sync.aligned.m16n8k16.row.col.f32.f16.f16.f32 "
        "{%0,%1,%2,%3},{%4,%5,%6,%7},{%8,%9},{%0,%1,%2,%3};"
        : "+f"(c[0]), "+f"(c[1]), "+f"(c[2]), "+f"(c[3])
        : "r"(a[0]), "r"(a[1]), "r"(a[2]), "r"(a[3]), "r"(b[0]), "r"(b[1]));
}

// smem: 3 stages x 32KB (A 16K | B 16K), then bias, then token idx
#define OFF_A    0
#define OFF_B    16384
#define STAGE_B  32768
#define OFF_BIAS 98304
#define OFF_TOK  98816
#define SMEM_REQ (99328 + 128)

// ---------------- init -----------------------------------------------------
__global__ void init_kernel() {
    int i = blockIdx.x * blockDim.x + threadIdx.x;
    if (i < E_EXP) { g_counts[i] = 0; g_cursor[i] = 0; }
    if (i < MAX_SLOTS) g_tok[i] = -1;
}

// ---------------- router ---------------------------------------------------
__global__ void router_kernel(const float* __restrict__ x,
                              const float* __restrict__ Wg,
                              const float* __restrict__ bg) {
    int t    = (blockIdx.x * blockDim.x + threadIdx.x) >> 5;
    int lane = threadIdx.x & 31;
    if (t >= T_TOK) return;
    const float* xr = x + (size_t)t * D_DIM;

    float acc[E_EXP];
#pragma unroll
    for (int e = 0; e < E_EXP; e++) acc[e] = 0.f;
    for (int d = lane; d < D_DIM; d += 32) {
        float xv = xr[d];
        const float4* w = reinterpret_cast<const float4*>(Wg + (size_t)d * E_EXP);
        float4 wa = w[0], wb = w[1];
        acc[0] = fmaf(xv, wa.x, acc[0]); acc[1] = fmaf(xv, wa.y, acc[1]);
        acc[2] = fmaf(xv, wa.z, acc[2]); acc[3] = fmaf(xv, wa.w, acc[3]);
        acc[4] = fmaf(xv, wb.x, acc[4]); acc[5] = fmaf(xv, wb.y, acc[5]);
        acc[6] = fmaf(xv, wb.z, acc[6]); acc[7] = fmaf(xv, wb.w, acc[7]);
    }
#pragma unroll
    for (int e = 0; e < E_EXP; e++)
#pragma unroll
        for (int off = 16; off; off >>= 1)
            acc[e] += __shfl_xor_sync(0xffffffffu, acc[e], off);

    if (lane == 0) {
        float l[E_EXP];
#pragma unroll
        for (int e = 0; e < E_EXP; e++) l[e] = acc[e] + bg[e];
        float m = l[0];
#pragma unroll
        for (int e = 1; e < E_EXP; e++) m = fmaxf(m, l[e]);
        float s = 0.f;
#pragma unroll
        for (int e = 0; e < E_EXP; e++) { l[e] = expf(l[e] - m); s += l[e]; }
        float inv = 1.f / s;
        int i0 = 0;
#pragma unroll
        for (int e = 1; e < E_EXP; e++) if (l[e] > l[i0]) i0 = e;
        int i1 = (i0 == 0) ? 1 : 0;
#pragma unroll
        for (int e = 0; e < E_EXP; e++)
            if (e != i0 && l[e] > l[i1]) i1 = e;
        g_topi[2 * t + 0] = i0;  g_topw[2 * t + 0] = l[i0] * inv;
        g_topi[2 * t + 1] = i1;  g_topw[2 * t + 1] = l[i1] * inv;
        atomicAdd(&g_counts[i0], 1);
        atomicAdd(&g_counts[i1], 1);
    }
}

// ---------------- scan -----------------------------------------------------
__global__ void scan_kernel() {
    if (threadIdx.x == 0) {
        int o = 0;
        for (int e = 0; e < E_EXP; e++) {
            g_offp[e] = o;
            o += ((g_counts[e] + BM - 1) / BM) * BM;
        }
        g_offp[E_EXP] = o;
    }
    __syncthreads();
    for (int m = threadIdx.x; m < MAX_TILES; m += blockDim.x) {
        int s = m * BM, e = -1;
        for (int i = 0; i < E_EXP; i++)
            if (s >= g_offp[i] && s < g_offp[i + 1]) e = i;
        g_tile_expert[m] = e;
    }
}

// ---------------- scatter --------------------------------------------------
__global__ void scatter_kernel() {
    int t = blockIdx.x * blockDim.x + threadIdx.x;
    if (t >= T_TOK) return;
#pragma unroll
    for (int k = 0; k < 2; k++) {
        int e    = g_topi[2 * t + k];
        int pos  = atomicAdd(&g_cursor[e], 1);
        int slot = g_offp[e] + pos;
        g_tok[slot] = t;
        g_slotof[2 * t + k] = slot;
    }
}

// ---------------- weight transpose + fp16 convert --------------------------
__global__ void wsplit_kernel(const float* __restrict__ W1,
                              const float* __restrict__ W2) {
    __shared__ float t[32][33];
    int b = blockIdx.x;
    const float* W; __half* oh; int K, N, e, nt, kt;
    if (b < 32768) {
        W = W1; oh = g_w1; K = D_DIM; N = H_DIM;
        e = b >> 12; int r = b & 4095; nt = r & 127; kt = r >> 7;
    } else {
        int b2 = b - 32768;
        W = W2; oh = g_w2; K = H_DIM; N = D_DIM;
        e = b2 >> 12; int r = b2 & 4095; nt = r & 31; kt = r >> 5;
    }
    int n0 = nt * 32, k0 = kt * 32;
    int tx = threadIdx.x, ty = threadIdx.y;
    const float* We = W + (size_t)e * K * N;
#pragma unroll
    for (int i = 0; i < 32; i += 8)
        t[ty + i][tx] = We[(size_t)(k0 + ty + i) * N + n0 + tx];
    __syncthreads();
    __half* ohe = oh + (size_t)e * K * N;
#pragma unroll
    for (int i = 0; i < 32; i += 8) {
        float v = t[tx][ty + i];
        ohe[(size_t)(n0 + ty + i) * K + (k0 + tx)] = __float2half_rn(v);
    }
}

// ---------------- x fp16 convert -------------------------------------------
__global__ void xsplit_kernel(const float* __restrict__ x) {
    int i = blockIdx.x * blockDim.x + threadIdx.x;     // over T*D/4
    float4 v = reinterpret_cast<const float4*>(x)[i];
    __half2 p0 = __floats2half2_rn(v.x, v.y);
    __half2 p1 = __floats2half2_rn(v.z, v.w);
    uint2 o;
    o.x = *(uint32_t*)&p0;
    o.y = *(uint32_t*)&p1;
    reinterpret_cast<uint2*>(g_x16)[i] = o;
}

// ---------------- HMMA GEMM (single fp16, k-chunk 64) ----------------------
// PHASE 1: h = gelu( gather(x16) @ W1[e]^T + b1 ) -> g_h16
// PHASE 2: y =        h16        @ W2[e]^T + b2   -> g_y
// 128x128 tile, 256 thr, warp 32x64, k-chunk 64, 3-stage cp.async ring.
// B fragments software-pipelined across the j-loop to hide LDS latency.
template <int PHASE>
__global__ void __launch_bounds__(256, 2) gemm_mma(const float* __restrict__ bias) {
    constexpr int K  = (PHASE == 1) ? D_DIM : H_DIM;
    constexpr int N  = (PHASE == 1) ? H_DIM : D_DIM;
    constexpr int NC = K / 64;

    int mt_blk = blockIdx.y;
    int e = g_tile_expert[mt_blk];
    if (e < 0) return;
    int m0 = mt_blk * BM, n0 = blockIdx.x * 128;

    extern __shared__ char dyn_smem[];
    char* sm = (char*)(((uintptr_t)dyn_smem + 127) & ~(uintptr_t)127);
    uint32_t sb = s2u(sm);

    int tid  = threadIdx.x;
    int lane = tid & 31, wid = tid >> 5;
    int wm = wid >> 1, wn = wid & 1;

    float* bias_s = (float*)(sm + OFF_BIAS);
    int*   tok_s  = (int*)(sm + OFF_TOK);

    if (tid < 128) {
        bias_s[tid] = bias[(size_t)e * N + n0 + tid];
        if (PHASE == 1) {
            int tk = g_tok[m0 + tid];
            tok_s[tid] = (tk < 0) ? 0 : tk;
        } else {
            tok_s[tid] = m0 + tid;
        }
    }
    __syncthreads();

    const __half* A_g = (PHASE == 1) ? g_x16 : g_h16;
    const __half* B_g = ((PHASE == 1) ? g_w1 : g_w2) + ((size_t)e * N + n0) * K;

    // ldmatrix lane rows (128B rows, chunk ^ (row&7) swizzle)
    int q = lane >> 3, r = lane & 7;
    int rowA_[2], rowB_[4];
#pragma unroll
    for (int mt = 0; mt < 2; mt++)
        rowA_[mt] = wm * 32 + mt * 16 + (q & 1) * 8 + r;
#pragma unroll
    for (int j = 0; j < 4; j++)
        rowB_[j] = wn * 64 + j * 16 + (q >> 1) * 8 + r;
    int qhA = q >> 1;     // k-chunk select bit for A fragments
    int qhB = q & 1;      // k-chunk select bit for B fragments

    float acc[2][8][4];
#pragma unroll
    for (int a = 0; a < 2; a++)
#pragma unroll
        for (int b = 0; b < 8; b++)
#pragma unroll
            for (int c = 0; c < 4; c++) acc[a][b][c] = 0.f;

    // stage loader: 4 x 16B per array per thread (A, B); row=128B, 8 chunks
    auto load_stage = [&](int c) {
        if (c < NC) {
            int k0 = c * 64;
            uint32_t sbs = sb + (uint32_t)(c % 3) * STAGE_B;
#pragma unroll
            for (int i = 0; i < 4; i++) {
                int t = tid + i * 256;
                int row = t >> 3, chunk = t & 7;
                uint32_t soff = (uint32_t)row * 128 +
                                (((uint32_t)(chunk ^ (row & 7))) << 4);
                int kk = k0 + chunk * 8;
                cpa16(sbs + OFF_A + soff, A_g + (size_t)tok_s[row] * K + kk);
                cpa16(sbs + OFF_B + soff, B_g + (size_t)row * K + kk);
            }
        }
        CP_COMMIT();
    };

    load_stage(0);
    load_stage(1);

    auto boffs = [&](int slice, int j) -> uint32_t {
        int row = rowB_[j];
        return (uint32_t)row * 128 +
               (((uint32_t)((slice * 2 + qhB) ^ (row & 7))) << 4);
    };

    for (int c = 0; c < NC; ++c) {
        CP_WAITG(1);
        __syncthreads();
        load_stage(c + 2);                 // 2-deep prefetch into free ring slot
        uint32_t sbs = sb + (uint32_t)(c % 3) * STAGE_B;
#pragma unroll
        for (int slice = 0; slice < 4; slice++) {
            // preload B fragment for j=0 first, so A-ldsm latency overlaps it
            uint32_t bh_cur[4], bh_nxt[4];
            LDSM4(bh_cur[0], bh_cur[1], bh_cur[2], bh_cur[3],
                  sbs + OFF_B + boffs(slice, 0));
            uint32_t ah[2][4];
#pragma unroll
            for (int mt = 0; mt < 2; mt++) {
                int row = rowA_[mt];
                uint32_t off = (uint32_t)row * 128 +
                    (((uint32_t)((slice * 2 + qhA) ^ (row & 7))) << 4);
                LDSM4(ah[mt][0], ah[mt][1], ah[mt][2], ah[mt][3],
                      sbs + OFF_A + off);
            }
#pragma unroll
            for (int j = 0; j < 4; j++) {
                if (j < 3)
                    LDSM4(bh_nxt[0], bh_nxt[1], bh_nxt[2], bh_nxt[3],
                          sbs + OFF_B + boffs(slice, j + 1));
#pragma unroll
                for (int mt = 0; mt < 2; mt++) {
#pragma unroll
                    for (int jj = 0; jj < 2; jj++)
                        mma16816(acc[mt][j * 2 + jj], ah[mt], bh_cur + jj * 2);
                }
#pragma unroll
                for (int u = 0; u < 4; u++) bh_cur[u] = bh_nxt[u];
            }
        }
    }

    // ---------------- epilogue (registers -> global) ----------------
    int g = lane >> 2, tc = lane & 3;
#pragma unroll
    for (int mt = 0; mt < 2; mt++) {
        int rowb = m0 + wm * 32 + mt * 16 + g;
#pragma unroll
        for (int h = 0; h < 2; h++) {
            int row = rowb + h * 8;
            size_t base = (size_t)row * N + n0 + wn * 64 + tc * 2;
#pragma unroll
            for (int nt = 0; nt < 8; nt++) {
                int nb = wn * 64 + nt * 8 + tc * 2;
                float u0 = acc[mt][nt][h * 2 + 0] + bias_s[nb];
                float u1 = acc[mt][nt][h * 2 + 1] + bias_s[nb + 1];
                if (PHASE == 1) {
                    u0 = 0.5f * u0 * (1.0f + erff(u0 * 0.7071067811865476f));
                    u1 = 0.5f * u1 * (1.0f + erff(u1 * 0.7071067811865476f));
                    __half2 p = __floats2half2_rn(u0, u1);
                    *(uint32_t*)(g_h16 + base + nt * 8) = *(uint32_t*)&p;
                } else {
                    float2 v = make_float2(u0, u1);
                    *(float2*)(g_y + base + nt * 8) = v;
                }
            }
        }
    }
}

// ---------------- combine --------------------------------------------------
__global__ void combine_kernel(float* __restrict__ out) {
    int i = blockIdx.x * blockDim.x + threadIdx.x;
    constexpr int Q = D_DIM / 4;
    if (i >= T_TOK * Q) return;
    int t = i / Q, qq = i - t * Q;
    int s0 = g_slotof[2 * t + 0], s1 = g_slotof[2 * t + 1];
    float w0 = g_topw[2 * t + 0], w1 = g_topw[2 * t + 1];
    const float4* y4 = reinterpret_cast<const float4*>(g_y);
    float4 a = y4[(size_t)s0 * Q + qq];
    float4 b = y4[(size_t)s1 * Q + qq];
    reinterpret_cast<float4*>(out)[i] =
        make_float4(fmaf(w0, a.x, w1 * b.x), fmaf(w0, a.y, w1 * b.y),
                    fmaf(w0, a.z, w1 * b.z), fmaf(w0, a.w, w1 * b.w));
}

// ---------------- launch ---------------------------------------------------
extern "C" void kernel_launch(void* const* d_in, const int* in_sizes, int n_in,
                              void* d_out, int out_size) {
    const float* x  = (const float*)d_in[0];
    const float* Wg = (const float*)d_in[1];
    const float* bg = (const float*)d_in[2];
    const float* W1 = (const float*)d_in[3];
    const float* b1 = (const float*)d_in[4];
    const float* W2 = (const float*)d_in[5];
    const float* b2 = (const float*)d_in[6];
    float* out = (float*)d_out;

    cudaFuncSetAttribute(gemm_mma<1>, cudaFuncAttributeMaxDynamicSharedMemorySize, SMEM_REQ);
    cudaFuncSetAttribute(gemm_mma<2>, cudaFuncAttributeMaxDynamicSharedMemorySize, SMEM_REQ);

    init_kernel<<<(MAX_SLOTS + 255) / 256, 256>>>();
    router_kernel<<<T_TOK / 8, 256>>>(x, Wg, bg);
    scan_kernel<<<1, 256>>>();
    scatter_kernel<<<T_TOK / 256, 256>>>();
    wsplit_kernel<<<65536, dim3(32, 8)>>>(W1, W2);
    xsplit_kernel<<<T_TOK * D_DIM / 4 / 256, 256>>>(x);
    gemm_mma<1><<<dim3(H_DIM / 128, MAX_TILES), 256, SMEM_REQ>>>(b1);
    gemm_mma<2><<<dim3(D_DIM / 128, MAX_TILES), 256, SMEM_REQ>>>(b2);
    combine_kernel<<<(T_TOK * (D_DIM / 4) + 255) / 256, 256>>>(out);
}

// round 12
// speedup vs baseline: 1.2286x; 1.0131x over previous
#include <cuda_runtime.h>
#include <cuda_bf16.h>
#include <cuda_fp16.h>
#include <math.h>
#include <stdint.h>

#define T_TOK   8192
#define D_DIM   1024
#define E_EXP   8
#define H_DIM   4096
#define BM      128
#define MAX_TILES (2 * T_TOK / BM + E_EXP)     // 136
#define MAX_SLOTS (MAX_TILES * BM)             // 17408

// ---------------- scratch (static device globals) --------------------------
__device__ int   g_counts[E_EXP];
__device__ int   g_cursor[E_EXP];
__device__ int   g_offp[E_EXP + 1];
__device__ int   g_tile_expert[MAX_TILES];
__device__ int   g_tok[MAX_SLOTS];
__device__ float g_wslot[MAX_SLOTS];
__device__ int   g_topi[T_TOK * 2];
__device__ float g_topw[T_TOK * 2];

// fp16 weights, transposed to [E][N][K] (K contiguous)
__device__ __half g_w1[(size_t)E_EXP * H_DIM * D_DIM];
__device__ __half g_w2[(size_t)E_EXP * D_DIM * H_DIM];
// fp16 activations
__device__ __half g_x16[(size_t)T_TOK * D_DIM];
__device__ __half g_h16[(size_t)MAX_SLOTS * H_DIM];

// ---------------- helpers --------------------------------------------------
__device__ __forceinline__ uint32_t s2u(const void* p) {
    uint32_t a;
    asm("{ .reg .u64 t; cvta.to.shared.u64 t, %1; cvt.u32.u64 %0, t; }"
        : "=r"(a) : "l"(p));
    return a;
}
__device__ __forceinline__ void cpa16(uint32_t dst, const void* src) {
    asm volatile("cp.async.cg.shared.global [%0], [%1], 16;"
                 :: "r"(dst), "l"(src) : "memory");
}
#define CP_COMMIT()  asm volatile("cp.async.commit_group;" ::: "memory")
#define CP_WAITG(n)  asm volatile("cp.async.wait_group %0;" :: "n"(n) : "memory")

#define LDSM4(r0, r1, r2, r3, addr)                                         \
    asm volatile("ldmatrix.sync.aligned.m8n8.x4.shared.b16 {%0,%1,%2,%3},[%4];" \
                 : "=r"(r0), "=r"(r1), "=r"(r2), "=r"(r3) : "r"(addr))

__device__ __forceinline__ void mma16816(float* c, const uint32_t* a,
                                         const uint32_t* b) {
    asm volatile(
        "mma.sync.aligned.m16n8k16.row.col.f32.f16.f16.f32 "
        "{%0,%1,%2,%3},{%4,%5,%6,%7},{%8,%9},{%0,%1,%2,%3};"
        : "+f"(c[0]), "+f"(c[1]), "+f"(c[2]), "+f"(c[3])
        : "r"(a[0]), "r"(a[1]), "r"(a[2]), "r"(a[3]), "r"(b[0]), "r"(b[1]));
}

// smem: 3 stages x 32KB (A 16K | B 16K), bias, token idx, out-token, weight
#define OFF_A    0
#define OFF_B    16384
#define STAGE_B  32768
#define OFF_BIAS 98304
#define OFF_TOK  98816
#define OFF_OT   99328
#define OFF_W    99840
#define SMEM_REQ (100352 + 128)

// ---------------- init -----------------------------------------------------
__global__ void init_kernel() {
    int i = blockIdx.x * blockDim.x + threadIdx.x;
    if (i < E_EXP) { g_counts[i] = 0; g_cursor[i] = 0; }
    if (i < MAX_SLOTS) g_tok[i] = -1;
}

// ---------------- zero output ----------------------------------------------
__global__ void zero_out_kernel(float* __restrict__ out) {
    int i = blockIdx.x * blockDim.x + threadIdx.x;     // over T*D/4
    reinterpret_cast<float4*>(out)[i] = make_float4(0.f, 0.f, 0.f, 0.f);
}

// ---------------- router (+ fused x -> fp16 conversion) --------------------
__global__ void router_kernel(const float* __restrict__ x,
                              const float* __restrict__ Wg,
                              const float* __restrict__ bg) {
    int t    = (blockIdx.x * blockDim.x + threadIdx.x) >> 5;
    int lane = threadIdx.x & 31;
    if (t >= T_TOK) return;
    const float* xr = x + (size_t)t * D_DIM;

    float acc[E_EXP];
#pragma unroll
    for (int e = 0; e < E_EXP; e++) acc[e] = 0.f;
    for (int d = lane * 2; d < D_DIM; d += 64) {
        float2 xv2 = *(const float2*)(xr + d);
        // fused fp16 conversion (coalesced 128B warp store)
        __half2 hp = __floats2half2_rn(xv2.x, xv2.y);
        *(uint32_t*)(g_x16 + (size_t)t * D_DIM + d) = *(uint32_t*)&hp;

        const float4* w0 = reinterpret_cast<const float4*>(Wg + (size_t)d * E_EXP);
        const float4* w1 = reinterpret_cast<const float4*>(Wg + (size_t)(d + 1) * E_EXP);
        float4 wa = w0[0], wb = w0[1], wc = w1[0], wd = w1[1];
        acc[0] = fmaf(xv2.x, wa.x, fmaf(xv2.y, wc.x, acc[0]));
        acc[1] = fmaf(xv2.x, wa.y, fmaf(xv2.y, wc.y, acc[1]));
        acc[2] = fmaf(xv2.x, wa.z, fmaf(xv2.y, wc.z, acc[2]));
        acc[3] = fmaf(xv2.x, wa.w, fmaf(xv2.y, wc.w, acc[3]));
        acc[4] = fmaf(xv2.x, wb.x, fmaf(xv2.y, wd.x, acc[4]));
        acc[5] = fmaf(xv2.x, wb.y, fmaf(xv2.y, wd.y, acc[5]));
        acc[6] = fmaf(xv2.x, wb.z, fmaf(xv2.y, wd.z, acc[6]));
        acc[7] = fmaf(xv2.x, wb.w, fmaf(xv2.y, wd.w, acc[7]));
    }
#pragma unroll
    for (int e = 0; e < E_EXP; e++)
#pragma unroll
        for (int off = 16; off; off >>= 1)
            acc[e] += __shfl_xor_sync(0xffffffffu, acc[e], off);

    if (lane == 0) {
        float l[E_EXP];
#pragma unroll
        for (int e = 0; e < E_EXP; e++) l[e] = acc[e] + bg[e];
        float m = l[0];
#pragma unroll
        for (int e = 1; e < E_EXP; e++) m = fmaxf(m, l[e]);
        float s = 0.f;
#pragma unroll
        for (int e = 0; e < E_EXP; e++) { l[e] = expf(l[e] - m); s += l[e]; }
        float inv = 1.f / s;
        int i0 = 0;
#pragma unroll
        for (int e = 1; e < E_EXP; e++) if (l[e] > l[i0]) i0 = e;
        int i1 = (i0 == 0) ? 1 : 0;
#pragma unroll
        for (int e = 0; e < E_EXP; e++)
            if (e != i0 && l[e] > l[i1]) i1 = e;
        g_topi[2 * t + 0] = i0;  g_topw[2 * t + 0] = l[i0] * inv;
        g_topi[2 * t + 1] = i1;  g_topw[2 * t + 1] = l[i1] * inv;
        atomicAdd(&g_counts[i0], 1);
        atomicAdd(&g_counts[i1], 1);
    }
}

// ---------------- scan -----------------------------------------------------
__global__ void scan_kernel() {
    if (threadIdx.x == 0) {
        int o = 0;
        for (int e = 0; e < E_EXP; e++) {
            g_offp[e] = o;
            o += ((g_counts[e] + BM - 1) / BM) * BM;
        }
        g_offp[E_EXP] = o;
    }
    __syncthreads();
    for (int m = threadIdx.x; m < MAX_TILES; m += blockDim.x) {
        int s = m * BM, e = -1;
        for (int i = 0; i < E_EXP; i++)
            if (s >= g_offp[i] && s < g_offp[i + 1]) e = i;
        g_tile_expert[m] = e;
    }
}

// ---------------- scatter --------------------------------------------------
__global__ void scatter_kernel() {
    int t = blockIdx.x * blockDim.x + threadIdx.x;
    if (t >= T_TOK) return;
#pragma unroll
    for (int k = 0; k < 2; k++) {
        int e    = g_topi[2 * t + k];
        int pos  = atomicAdd(&g_cursor[e], 1);
        int slot = g_offp[e] + pos;
        g_tok[slot]   = t;
        g_wslot[slot] = g_topw[2 * t + k];
    }
}

// ---------------- weight transpose + fp16 convert --------------------------
__global__ void wsplit_kernel(const float* __restrict__ W1,
                              const float* __restrict__ W2) {
    __shared__ float t[32][33];
    int b = blockIdx.x;
    const float* W; __half* oh; int K, N, e, nt, kt;
    if (b < 32768) {
        W = W1; oh = g_w1; K = D_DIM; N = H_DIM;
        e = b >> 12; int r = b & 4095; nt = r & 127; kt = r >> 7;
    } else {
        int b2 = b - 32768;
        W = W2; oh = g_w2; K = H_DIM; N = D_DIM;
        e = b2 >> 12; int r = b2 & 4095; nt = r & 31; kt = r >> 5;
    }
    int n0 = nt * 32, k0 = kt * 32;
    int tx = threadIdx.x, ty = threadIdx.y;
    const float* We = W + (size_t)e * K * N;
#pragma unroll
    for (int i = 0; i < 32; i += 8)
        t[ty + i][tx] = We[(size_t)(k0 + ty + i) * N + n0 + tx];
    __syncthreads();
    __half* ohe = oh + (size_t)e * K * N;
#pragma unroll
    for (int i = 0; i < 32; i += 8) {
        float v = t[tx][ty + i];
        ohe[(size_t)(n0 + ty + i) * K + (k0 + tx)] = __float2half_rn(v);
    }
}

// ---------------- HMMA GEMM (single fp16, k-chunk 64) ----------------------
// PHASE 1: h = gelu( gather(x16) @ W1[e]^T + b1 ) -> g_h16
// PHASE 2: out[tok] += w * ( h16 @ W2[e]^T + b2 )   (fused combine, RED.F32)
// 128x128 tile, 256 thr, warp 32x64, k-chunk 64, 3-stage cp.async ring.
template <int PHASE>
__global__ void __launch_bounds__(256, 2) gemm_mma(const float* __restrict__ bias,
                                                   float* __restrict__ out) {
    constexpr int K  = (PHASE == 1) ? D_DIM : H_DIM;
    constexpr int N  = (PHASE == 1) ? H_DIM : D_DIM;
    constexpr int NC = K / 64;

    int mt_blk = blockIdx.y;
    int e = g_tile_expert[mt_blk];
    if (e < 0) return;
    int m0 = mt_blk * BM, n0 = blockIdx.x * 128;

    extern __shared__ char dyn_smem[];
    char* sm = (char*)(((uintptr_t)dyn_smem + 127) & ~(uintptr_t)127);
    uint32_t sb = s2u(sm);

    int tid  = threadIdx.x;
    int lane = tid & 31, wid = tid >> 5;
    int wm = wid >> 1, wn = wid & 1;

    float* bias_s = (float*)(sm + OFF_BIAS);
    int*   tok_s  = (int*)(sm + OFF_TOK);
    int*   ot_s   = (int*)(sm + OFF_OT);
    float* w_s    = (float*)(sm + OFF_W);

    if (tid < 128) {
        bias_s[tid] = bias[(size_t)e * N + n0 + tid];
        if (PHASE == 1) {
            int tk = g_tok[m0 + tid];
            tok_s[tid] = (tk < 0) ? 0 : tk;
        } else {
            tok_s[tid] = m0 + tid;
            ot_s[tid]  = g_tok[m0 + tid];          // may be -1 (padding)
            w_s[tid]   = g_wslot[m0 + tid];
        }
    }
    __syncthreads();

    const __half* A_g = (PHASE == 1) ? g_x16 : g_h16;
    const __half* B_g = ((PHASE == 1) ? g_w1 : g_w2) + ((size_t)e * N + n0) * K;

    // ldmatrix lane rows (128B rows, chunk ^ (row&7) swizzle)
    int q = lane >> 3, r = lane & 7;
    int rowA_[2], rowB_[4];
#pragma unroll
    for (int mt = 0; mt < 2; mt++)
        rowA_[mt] = wm * 32 + mt * 16 + (q & 1) * 8 + r;
#pragma unroll
    for (int j = 0; j < 4; j++)
        rowB_[j] = wn * 64 + j * 16 + (q >> 1) * 8 + r;
    int qhA = q >> 1;     // k-chunk select bit for A fragments
    int qhB = q & 1;      // k-chunk select bit for B fragments

    float acc[2][8][4];
#pragma unroll
    for (int a = 0; a < 2; a++)
#pragma unroll
        for (int b = 0; b < 8; b++)
#pragma unroll
            for (int c = 0; c < 4; c++) acc[a][b][c] = 0.f;

    // stage loader: 4 x 16B per array per thread (A, B); row=128B, 8 chunks
    auto load_stage = [&](int c) {
        if (c < NC) {
            int k0 = c * 64;
            uint32_t sbs = sb + (uint32_t)(c % 3) * STAGE_B;
#pragma unroll
            for (int i = 0; i < 4; i++) {
                int t = tid + i * 256;
                int row = t >> 3, chunk = t & 7;
                uint32_t soff = (uint32_t)row * 128 +
                                (((uint32_t)(chunk ^ (row & 7))) << 4);
                int kk = k0 + chunk * 8;
                cpa16(sbs + OFF_A + soff, A_g + (size_t)tok_s[row] * K + kk);
                cpa16(sbs + OFF_B + soff, B_g + (size_t)row * K + kk);
            }
        }
        CP_COMMIT();
    };

    load_stage(0);
    load_stage(1);

    for (int c = 0; c < NC; ++c) {
        CP_WAITG(1);
        __syncthreads();
        load_stage(c + 2);                 // 2-deep prefetch into free ring slot
        uint32_t sbs = sb + (uint32_t)(c % 3) * STAGE_B;
#pragma unroll
        for (int slice = 0; slice < 4; slice++) {
            uint32_t ah[2][4];
#pragma unroll
            for (int mt = 0; mt < 2; mt++) {
                int row = rowA_[mt];
                uint32_t off = (uint32_t)row * 128 +
                    (((uint32_t)((slice * 2 + qhA) ^ (row & 7))) << 4);
                LDSM4(ah[mt][0], ah[mt][1], ah[mt][2], ah[mt][3],
                      sbs + OFF_A + off);
            }
#pragma unroll
            for (int j = 0; j < 4; j++) {
                int row = rowB_[j];
                uint32_t off = (uint32_t)row * 128 +
                    (((uint32_t)((slice * 2 + qhB) ^ (row & 7))) << 4);
                uint32_t bh[4];
                LDSM4(bh[0], bh[1], bh[2], bh[3], sbs + OFF_B + off);
#pragma unroll
                for (int mt = 0; mt < 2; mt++) {
#pragma unroll
                    for (int jj = 0; jj < 2; jj++)
                        mma16816(acc[mt][j * 2 + jj], ah[mt], bh + jj * 2);
                }
            }
        }
    }

    // ---------------- epilogue ----------------
    int g = lane >> 2, tc = lane & 3;
#pragma unroll
    for (int mt = 0; mt < 2; mt++) {
        int rowl = wm * 32 + mt * 16 + g;
#pragma unroll
        for (int h = 0; h < 2; h++) {
            int rl = rowl + h * 8;
            if (PHASE == 1) {
                size_t base = (size_t)(m0 + rl) * N + n0 + wn * 64 + tc * 2;
#pragma unroll
                for (int nt = 0; nt < 8; nt++) {
                    int nb = wn * 64 + nt * 8 + tc * 2;
                    float u0 = acc[mt][nt][h * 2 + 0] + bias_s[nb];
                    float u1 = acc[mt][nt][h * 2 + 1] + bias_s[nb + 1];
                    u0 = 0.5f * u0 * (1.0f + erff(u0 * 0.7071067811865476f));
                    u1 = 0.5f * u1 * (1.0f + erff(u1 * 0.7071067811865476f));
                    __half2 p = __floats2half2_rn(u0, u1);
                    *(uint32_t*)(g_h16 + base + nt * 8) = *(uint32_t*)&p;
                }
            } else {
                int   ot = ot_s[rl];
                float w  = w_s[rl];
                if (ot >= 0) {
                    float* orow = out + (size_t)ot * D_DIM + n0 + wn * 64 + tc * 2;
#pragma unroll
                    for (int nt = 0; nt < 8; nt++) {
                        int nb = wn * 64 + nt * 8 + tc * 2;
                        float u0 = acc[mt][nt][h * 2 + 0] + bias_s[nb];
                        float u1 = acc[mt][nt][h * 2 + 1] + bias_s[nb + 1];
                        atomicAdd(orow + nt * 8 + 0, w * u0);
                        atomicAdd(orow + nt * 8 + 1, w * u1);
                    }
                }
            }
        }
    }
}

// ---------------- launch ---------------------------------------------------
extern "C" void kernel_launch(void* const* d_in, const int* in_sizes, int n_in,
                              void* d_out, int out_size) {
    const float* x  = (const float*)d_in[0];
    const float* Wg = (const float*)d_in[1];
    const float* bg = (const float*)d_in[2];
    const float* W1 = (const float*)d_in[3];
    const float* b1 = (const float*)d_in[4];
    const float* W2 = (const float*)d_in[5];
    const float* b2 = (const float*)d_in[6];
    float* out = (float*)d_out;

    cudaFuncSetAttribute(gemm_mma<1>, cudaFuncAttributeMaxDynamicSharedMemorySize, SMEM_REQ);
    cudaFuncSetAttribute(gemm_mma<2>, cudaFuncAttributeMaxDynamicSharedMemorySize, SMEM_REQ);

    init_kernel<<<(MAX_SLOTS + 255) / 256, 256>>>();
    zero_out_kernel<<<T_TOK * D_DIM / 4 / 256, 256>>>(out);
    router_kernel<<<T_TOK / 8, 256>>>(x, Wg, bg);
    scan_kernel<<<1, 256>>>();
    scatter_kernel<<<T_TOK / 256, 256>>>();
    wsplit_kernel<<<65536, dim3(32, 8)>>>(W1, W2);
    gemm_mma<1><<<dim3(H_DIM / 128, MAX_TILES), 256, SMEM_REQ>>>(b1, out);
    gemm_mma<2><<<dim3(D_DIM / 128, MAX_TILES), 256, SMEM_REQ>>>(b2, out);
}

// round 16
// speedup vs baseline: 1.2341x; 1.0044x over previous
#include <cuda_runtime.h>
#include <cuda_bf16.h>
#include <cuda_fp16.h>
#include <math.h>
#include <stdint.h>

#define T_TOK   8192
#define D_DIM   1024
#define E_EXP   8
#define H_DIM   4096
#define BM      128
#define MAX_TILES (2 * T_TOK / BM + E_EXP)     // 136
#define MAX_SLOTS (MAX_TILES * BM)             // 17408

// fused-prep grid layout
#define WC_N    65536                           // weight-convert blocks
#define Z_BASE  WC_N
#define Z_N     (T_TOK * D_DIM / 4 / 256)       // 8192
#define R_BASE  (Z_BASE + Z_N)
#define R_N     (T_TOK / 8)                     // 1024
#define TI_BASE (R_BASE + R_N)
#define TI_N    ((MAX_SLOTS + 255) / 256)       // 68
#define PREP_GRID (TI_BASE + TI_N)

// ---------------- scratch (static device globals) --------------------------
__device__ int   g_counts[E_EXP];
__device__ int   g_cursor[E_EXP];
__device__ int   g_offp[E_EXP + 1];
__device__ int   g_tile_expert[MAX_TILES];
__device__ int   g_tok[MAX_SLOTS];
__device__ float g_wslot[MAX_SLOTS];
__device__ int   g_topi[T_TOK * 2];
__device__ float g_topw[T_TOK * 2];

// fp16 weights, transposed to [E][N][K] (K contiguous)
__device__ __half g_w1[(size_t)E_EXP * H_DIM * D_DIM];
__device__ __half g_w2[(size_t)E_EXP * D_DIM * H_DIM];
// fp16 activations
__device__ __half g_x16[(size_t)T_TOK * D_DIM];
__device__ __half g_h16[(size_t)MAX_SLOTS * H_DIM];

// ---------------- helpers --------------------------------------------------
__device__ __forceinline__ uint32_t s2u(const void* p) {
    uint32_t a;
    asm("{ .reg .u64 t; cvta.to.shared.u64 t, %1; cvt.u32.u64 %0, t; }"
        : "=r"(a) : "l"(p));
    return a;
}
__device__ __forceinline__ void cpa16(uint32_t dst, const void* src) {
    asm volatile("cp.async.cg.shared.global [%0], [%1], 16;"
                 :: "r"(dst), "l"(src) : "memory");
}
#define CP_COMMIT()  asm volatile("cp.async.commit_group;" ::: "memory")
#define CP_WAITG(n)  asm volatile("cp.async.wait_group %0;" :: "n"(n) : "memory")

#define LDSM4(r0, r1, r2, r3, addr)                                         \
    asm volatile("ldmatrix.sync.aligned.m8n8.x4.shared.b16 {%0,%1,%2,%3},[%4];" \
                 : "=r"(r0), "=r"(r1), "=r"(r2), "=r"(r3) : "r"(addr))

__device__ __forceinline__ void mma16816(float* c, const uint32_t* a,
                                         const uint32_t* b) {
    asm volatile(
        "mma.sync.aligned.m16n8k16.row.col.f32.f16.f16.f32 "
        "{%0,%1,%2,%3},{%4,%5,%6,%7},{%8,%9},{%0,%1,%2,%3};"
        : "+f"(c[0]), "+f"(c[1]), "+f"(c[2]), "+f"(c[3])
        : "r"(a[0]), "r"(a[1]), "r"(a[2]), "r"(a[3]), "r"(b[0]), "r"(b[1]));
}

// smem: 3 stages x 32KB (A 16K | B 16K), bias, token idx, out-token, weight
#define OFF_A    0
#define OFF_B    16384
#define STAGE_B  32768
#define OFF_BIAS 98304
#define OFF_TOK  98816
#define OFF_OT   99328
#define OFF_W    99840
#define SMEM_REQ (100352 + 128)

// ---------------- tiny init (counters only) ---------------------------------
__global__ void init_counters_kernel() {
    int i = threadIdx.x;
    if (i < E_EXP) { g_counts[i] = 0; g_cursor[i] = 0; }
}

// ---------------- fused prep: wconv W1/W2 + zero_out + router + tok init ----
__global__ void fused_prep_kernel(const float* __restrict__ x,
                                  const float* __restrict__ Wg,
                                  const float* __restrict__ bg,
                                  const float* __restrict__ W1,
                                  const float* __restrict__ W2,
                                  float* __restrict__ out) {
    __shared__ float ts[32][33];
    int b   = blockIdx.x;
    int tid = threadIdx.x;

    if (b < WC_N) {
        // ---- weight transpose + fp16 convert: 32x32 tile per block ----
        const float* W; __half* oh; int KD, ND, e, nt, kt;
        if (b < 32768) {
            W = W1; oh = g_w1; KD = D_DIM; ND = H_DIM;
            e = b >> 12; int r = b & 4095; nt = r & 127; kt = r >> 7;
        } else {
            int b2 = b - 32768;
            W = W2; oh = g_w2; KD = H_DIM; ND = D_DIM;
            e = b2 >> 12; int r = b2 & 4095; nt = r & 31; kt = r >> 5;
        }
        int n0 = nt * 32, k0 = kt * 32;
        int tx = tid & 31, ty = tid >> 5;
        const float* We = W + (size_t)e * KD * ND;
#pragma unroll
        for (int i = 0; i < 32; i += 8)
            ts[ty + i][tx] = We[(size_t)(k0 + ty + i) * ND + n0 + tx];
        __syncthreads();
        __half* ohe = oh + (size_t)e * KD * ND;
#pragma unroll
        for (int i = 0; i < 32; i += 8) {
            float v = ts[tx][ty + i];
            ohe[(size_t)(n0 + ty + i) * KD + (k0 + tx)] = __float2half_rn(v);
        }
        return;
    }
    if (b < R_BASE) {
        // ---- zero output ----
        int i = (b - Z_BASE) * 256 + tid;
        reinterpret_cast<float4*>(out)[i] = make_float4(0.f, 0.f, 0.f, 0.f);
        return;
    }
    if (b < TI_BASE) {
        // ---- router (+ fused x -> fp16 conversion); one warp per token ----
        int t    = (b - R_BASE) * 8 + (tid >> 5);
        int lane = tid & 31;
        const float* xr = x + (size_t)t * D_DIM;

        float acc[E_EXP];
#pragma unroll
        for (int e = 0; e < E_EXP; e++) acc[e] = 0.f;
        for (int d = lane * 2; d < D_DIM; d += 64) {
            float2 xv2 = *(const float2*)(xr + d);
            __half2 hp = __floats2half2_rn(xv2.x, xv2.y);
            *(uint32_t*)(g_x16 + (size_t)t * D_DIM + d) = *(uint32_t*)&hp;

            const float4* w0 = reinterpret_cast<const float4*>(Wg + (size_t)d * E_EXP);
            const float4* w1 = reinterpret_cast<const float4*>(Wg + (size_t)(d + 1) * E_EXP);
            float4 wa = w0[0], wb = w0[1], wc = w1[0], wd = w1[1];
            acc[0] = fmaf(xv2.x, wa.x, fmaf(xv2.y, wc.x, acc[0]));
            acc[1] = fmaf(xv2.x, wa.y, fmaf(xv2.y, wc.y, acc[1]));
            acc[2] = fmaf(xv2.x, wa.z, fmaf(xv2.y, wc.z, acc[2]));
            acc[3] = fmaf(xv2.x, wa.w, fmaf(xv2.y, wc.w, acc[3]));
            acc[4] = fmaf(xv2.x, wb.x, fmaf(xv2.y, wd.x, acc[4]));
            acc[5] = fmaf(xv2.x, wb.y, fmaf(xv2.y, wd.y, acc[5]));
            acc[6] = fmaf(xv2.x, wb.z, fmaf(xv2.y, wd.z, acc[6]));
            acc[7] = fmaf(xv2.x, wb.w, fmaf(xv2.y, wd.w, acc[7]));
        }
#pragma unroll
        for (int e = 0; e < E_EXP; e++)
#pragma unroll
            for (int off = 16; off; off >>= 1)
                acc[e] += __shfl_xor_sync(0xffffffffu, acc[e], off);

        if (lane == 0) {
            float l[E_EXP];
#pragma unroll
            for (int e = 0; e < E_EXP; e++) l[e] = acc[e] + bg[e];
            float m = l[0];
#pragma unroll
            for (int e = 1; e < E_EXP; e++) m = fmaxf(m, l[e]);
            float s = 0.f;
#pragma unroll
            for (int e = 0; e < E_EXP; e++) { l[e] = expf(l[e] - m); s += l[e]; }
            float inv = 1.f / s;
            int i0 = 0;
#pragma unroll
            for (int e = 1; e < E_EXP; e++) if (l[e] > l[i0]) i0 = e;
            int i1 = (i0 == 0) ? 1 : 0;
#pragma unroll
            for (int e = 0; e < E_EXP; e++)
                if (e != i0 && l[e] > l[i1]) i1 = e;
            g_topi[2 * t + 0] = i0;  g_topw[2 * t + 0] = l[i0] * inv;
            g_topi[2 * t + 1] = i1;  g_topw[2 * t + 1] = l[i1] * inv;
            atomicAdd(&g_counts[i0], 1);
            atomicAdd(&g_counts[i1], 1);
        }
        return;
    }
    // ---- g_tok init ----
    {
        int i = (b - TI_BASE) * 256 + tid;
        if (i < MAX_SLOTS) g_tok[i] = -1;
    }
}

// ---------------- scan -----------------------------------------------------
__global__ void scan_kernel() {
    if (threadIdx.x == 0) {
        int o = 0;
        for (int e = 0; e < E_EXP; e++) {
            g_offp[e] = o;
            o += ((g_counts[e] + BM - 1) / BM) * BM;
        }
        g_offp[E_EXP] = o;
    }
    __syncthreads();
    for (int m = threadIdx.x; m < MAX_TILES; m += blockDim.x) {
        int s = m * BM, e = -1;
        for (int i = 0; i < E_EXP; i++)
            if (s >= g_offp[i] && s < g_offp[i + 1]) e = i;
        g_tile_expert[m] = e;
    }
}

// ---------------- scatter --------------------------------------------------
__global__ void scatter_kernel() {
    int t = blockIdx.x * blockDim.x + threadIdx.x;
    if (t >= T_TOK) return;
#pragma unroll
    for (int k = 0; k < 2; k++) {
        int e    = g_topi[2 * t + k];
        int pos  = atomicAdd(&g_cursor[e], 1);
        int slot = g_offp[e] + pos;
        g_tok[slot]   = t;
        g_wslot[slot] = g_topw[2 * t + k];
    }
}

// ---------------- HMMA GEMM (single fp16, k-chunk 64) ----------------------
// PHASE 1: h = gelu( gather(x16) @ W1[e]^T + b1 ) -> g_h16
// PHASE 2: out[tok] += w * ( h16 @ W2[e]^T + b2 )   (fused combine, RED.F32)
template <int PHASE>
__global__ void __launch_bounds__(256, 2) gemm_mma(const float* __restrict__ bias,
                                                   float* __restrict__ out) {
    constexpr int K  = (PHASE == 1) ? D_DIM : H_DIM;
    constexpr int N  = (PHASE == 1) ? H_DIM : D_DIM;
    constexpr int NC = K / 64;

    int mt_blk = blockIdx.y;
    int e = g_tile_expert[mt_blk];
    if (e < 0) return;
    int m0 = mt_blk * BM, n0 = blockIdx.x * 128;

    extern __shared__ char dyn_smem[];
    char* sm = (char*)(((uintptr_t)dyn_smem + 127) & ~(uintptr_t)127);
    uint32_t sb = s2u(sm);

    int tid  = threadIdx.x;
    int lane = tid & 31, wid = tid >> 5;
    int wm = wid >> 1, wn = wid & 1;

    float* bias_s = (float*)(sm + OFF_BIAS);
    int*   tok_s  = (int*)(sm + OFF_TOK);
    int*   ot_s   = (int*)(sm + OFF_OT);
    float* w_s    = (float*)(sm + OFF_W);

    if (tid < 128) {
        bias_s[tid] = bias[(size_t)e * N + n0 + tid];
        if (PHASE == 1) {
            int tk = g_tok[m0 + tid];
            tok_s[tid] = (tk < 0) ? 0 : tk;
        } else {
            tok_s[tid] = m0 + tid;
            ot_s[tid]  = g_tok[m0 + tid];          // may be -1 (padding)
            w_s[tid]   = g_wslot[m0 + tid];
        }
    }
    __syncthreads();

    const __half* A_g = (PHASE == 1) ? g_x16 : g_h16;
    const __half* B_g = ((PHASE == 1) ? g_w1 : g_w2) + ((size_t)e * N + n0) * K;

    // ldmatrix lane rows (128B rows, chunk ^ (row&7) swizzle)
    int q = lane >> 3, r = lane & 7;
    int rowA_[2], rowB_[4];
#pragma unroll
    for (int mt = 0; mt < 2; mt++)
        rowA_[mt] = wm * 32 + mt * 16 + (q & 1) * 8 + r;
#pragma unroll
    for (int j = 0; j < 4; j++)
        rowB_[j] = wn * 64 + j * 16 + (q >> 1) * 8 + r;
    int qhA = q >> 1;
    int qhB = q & 1;

    float acc[2][8][4];
#pragma unroll
    for (int a = 0; a < 2; a++)
#pragma unroll
        for (int b = 0; b < 8; b++)
#pragma unroll
            for (int c = 0; c < 4; c++) acc[a][b][c] = 0.f;

    auto load_stage = [&](int c) {
        if (c < NC) {
            int k0 = c * 64;
            uint32_t sbs = sb + (uint32_t)(c % 3) * STAGE_B;
#pragma unroll
            for (int i = 0; i < 4; i++) {
                int t = tid + i * 256;
                int row = t >> 3, chunk = t & 7;
                uint32_t soff = (uint32_t)row * 128 +
                                (((uint32_t)(chunk ^ (row & 7))) << 4);
                int kk = k0 + chunk * 8;
                cpa16(sbs + OFF_A + soff, A_g + (size_t)tok_s[row] * K + kk);
                cpa16(sbs + OFF_B + soff, B_g + (size_t)row * K + kk);
            }
        }
        CP_COMMIT();
    };

    load_stage(0);
    load_stage(1);

    for (int c = 0; c < NC; ++c) {
        CP_WAITG(1);
        __syncthreads();
        load_stage(c + 2);
        uint32_t sbs = sb + (uint32_t)(c % 3) * STAGE_B;
#pragma unroll
        for (int slice = 0; slice < 4; slice++) {
            uint32_t ah[2][4];
#pragma unroll
            for (int mt = 0; mt < 2; mt++) {
                int row = rowA_[mt];
                uint32_t off = (uint32_t)row * 128 +
                    (((uint32_t)((slice * 2 + qhA) ^ (row & 7))) << 4);
                LDSM4(ah[mt][0], ah[mt][1], ah[mt][2], ah[mt][3],
                      sbs + OFF_A + off);
            }
#pragma unroll
            for (int j = 0; j < 4; j++) {
                int row = rowB_[j];
                uint32_t off = (uint32_t)row * 128 +
                    (((uint32_t)((slice * 2 + qhB) ^ (row & 7))) << 4);
                uint32_t bh[4];
                LDSM4(bh[0], bh[1], bh[2], bh[3], sbs + OFF_B + off);
#pragma unroll
                for (int mt = 0; mt < 2; mt++) {
#pragma unroll
                    for (int jj = 0; jj < 2; jj++)
                        mma16816(acc[mt][j * 2 + jj], ah[mt], bh + jj * 2);
                }
            }
        }
    }

    // ---------------- epilogue ----------------
    int g = lane >> 2, tc = lane & 3;
#pragma unroll
    for (int mt = 0; mt < 2; mt++) {
        int rowl = wm * 32 + mt * 16 + g;
#pragma unroll
        for (int h = 0; h < 2; h++) {
            int rl = rowl + h * 8;
            if (PHASE == 1) {
                size_t base = (size_t)(m0 + rl) * N + n0 + wn * 64 + tc * 2;
#pragma unroll
                for (int nt = 0; nt < 8; nt++) {
                    int nb = wn * 64 + nt * 8 + tc * 2;
                    float u0 = acc[mt][nt][h * 2 + 0] + bias_s[nb];
                    float u1 = acc[mt][nt][h * 2 + 1] + bias_s[nb + 1];
                    u0 = 0.5f * u0 * (1.0f + erff(u0 * 0.7071067811865476f));
                    u1 = 0.5f * u1 * (1.0f + erff(u1 * 0.7071067811865476f));
                    __half2 p = __floats2half2_rn(u0, u1);
                    *(uint32_t*)(g_h16 + base + nt * 8) = *(uint32_t*)&p;
                }
            } else {
                int   ot = ot_s[rl];
                float w  = w_s[rl];
                if (ot >= 0) {
                    float* orow = out + (size_t)ot * D_DIM + n0 + wn * 64 + tc * 2;
#pragma unroll
                    for (int nt = 0; nt < 8; nt++) {
                        int nb = wn * 64 + nt * 8 + tc * 2;
                        float u0 = acc[mt][nt][h * 2 + 0] + bias_s[nb];
                        float u1 = acc[mt][nt][h * 2 + 1] + bias_s[nb + 1];
                        atomicAdd(orow + nt * 8 + 0, w * u0);
                        atomicAdd(orow + nt * 8 + 1, w * u1);
                    }
                }
            }
        }
    }
}

// ---------------- launch (single stream; graph-capture safe) ----------------
extern "C" void kernel_launch(void* const* d_in, const int* in_sizes, int n_in,
                              void* d_out, int out_size) {
    const float* x  = (const float*)d_in[0];
    const float* Wg = (const float*)d_in[1];
    const float* bg = (const float*)d_in[2];
    const float* W1 = (const float*)d_in[3];
    const float* b1 = (const float*)d_in[4];
    const float* W2 = (const float*)d_in[5];
    const float* b2 = (const float*)d_in[6];
    float* out = (float*)d_out;

    cudaFuncSetAttribute(gemm_mma<1>, cudaFuncAttributeMaxDynamicSharedMemorySize, SMEM_REQ);
    cudaFuncSetAttribute(gemm_mma<2>, cudaFuncAttributeMaxDynamicSharedMemorySize, SMEM_REQ);

    init_counters_kernel<<<1, 256>>>();
    fused_prep_kernel<<<PREP_GRID, 256>>>(x, Wg, bg, W1, W2, out);
    scan_kernel<<<1, 256>>>();
    scatter_kernel<<<T_TOK / 256, 256>>>();
    gemm_mma<1><<<dim3(H_DIM / 128, MAX_TILES), 256, SMEM_REQ>>>(b1, out);
    gemm_mma<2><<<dim3(D_DIM / 128, MAX_TILES), 256, SMEM_REQ>>>(b2, out);
}

// round 17
// speedup vs baseline: 1.2433x; 1.0075x over previous
#include <cuda_runtime.h>
#include <cuda_bf16.h>
#include <cuda_fp16.h>
#include <math.h>
#include <stdint.h>

#define T_TOK   8192
#define D_DIM   1024
#define E_EXP   8
#define H_DIM   4096
#define BM      128
#define MAX_TILES (2 * T_TOK / BM + E_EXP)     // 136
#define MAX_SLOTS (MAX_TILES * BM)             // 17408

// fused-prep grid layout
#define WC_N    65536                           // weight-convert blocks
#define Z_BASE  WC_N
#define Z_N     (T_TOK * D_DIM / 4 / 256)       // 8192
#define R_BASE  (Z_BASE + Z_N)
#define R_N     (T_TOK / 8)                     // 1024
#define TI_BASE (R_BASE + R_N)
#define TI_N    ((MAX_SLOTS + 255) / 256)       // 68
#define PREP_GRID (TI_BASE + TI_N)

// ---------------- scratch (static device globals) --------------------------
__device__ int   g_counts[E_EXP];
__device__ int   g_cursor[E_EXP];
__device__ int   g_tile_expert[MAX_TILES];
__device__ int   g_tok[MAX_SLOTS];
__device__ float g_wslot[MAX_SLOTS];
__device__ int   g_topi[T_TOK * 2];
__device__ float g_topw[T_TOK * 2];

// fp16 weights, transposed to [E][N][K] (K contiguous)
__device__ __half g_w1[(size_t)E_EXP * H_DIM * D_DIM];
__device__ __half g_w2[(size_t)E_EXP * D_DIM * H_DIM];
// fp16 activations
__device__ __half g_x16[(size_t)T_TOK * D_DIM];
__device__ __half g_h16[(size_t)MAX_SLOTS * H_DIM];

// ---------------- helpers --------------------------------------------------
__device__ __forceinline__ uint32_t s2u(const void* p) {
    uint32_t a;
    asm("{ .reg .u64 t; cvta.to.shared.u64 t, %1; cvt.u32.u64 %0, t; }"
        : "=r"(a) : "l"(p));
    return a;
}
__device__ __forceinline__ void cpa16(uint32_t dst, const void* src) {
    asm volatile("cp.async.cg.shared.global [%0], [%1], 16;"
                 :: "r"(dst), "l"(src) : "memory");
}
#define CP_COMMIT()  asm volatile("cp.async.commit_group;" ::: "memory")
#define CP_WAITG(n)  asm volatile("cp.async.wait_group %0;" :: "n"(n) : "memory")

#define LDSM4(r0, r1, r2, r3, addr)                                         \
    asm volatile("ldmatrix.sync.aligned.m8n8.x4.shared.b16 {%0,%1,%2,%3},[%4];" \
                 : "=r"(r0), "=r"(r1), "=r"(r2), "=r"(r3) : "r"(addr))

__device__ __forceinline__ void mma16816(float* c, const uint32_t* a,
                                         const uint32_t* b) {
    asm volatile(
        "mma.sync.aligned.m16n8k16.row.col.f32.f16.f16.f32 "
        "{%0,%1,%2,%3},{%4,%5,%6,%7},{%8,%9},{%0,%1,%2,%3};"
        : "+f"(c[0]), "+f"(c[1]), "+f"(c[2]), "+f"(c[3])
        : "r"(a[0]), "r"(a[1]), "r"(a[2]), "r"(a[3]), "r"(b[0]), "r"(b[1]));
}

// smem: 3 stages x 32KB (A 16K | B 16K), bias, token idx, out-token, weight
#define OFF_A    0
#define OFF_B    16384
#define STAGE_B  32768
#define OFF_BIAS 98304
#define OFF_TOK  98816
#define OFF_OT   99328
#define OFF_W    99840
#define SMEM_REQ (100352 + 128)

// ---------------- fused prep: wconv W1/W2 + zero_out + router + tok init ----
__global__ void fused_prep_kernel(const float* __restrict__ x,
                                  const float* __restrict__ Wg,
                                  const float* __restrict__ bg,
                                  const float* __restrict__ W1,
                                  const float* __restrict__ W2,
                                  float* __restrict__ out) {
    __shared__ float ts[32][33];
    __shared__ int   s_cnt[E_EXP];
    int b   = blockIdx.x;
    int tid = threadIdx.x;

    if (b < WC_N) {
        // ---- weight transpose + fp16 convert: 32x32 tile per block ----
        const float* W; __half* oh; int KD, ND, e, nt, kt;
        if (b < 32768) {
            W = W1; oh = g_w1; KD = D_DIM; ND = H_DIM;
            e = b >> 12; int r = b & 4095; nt = r & 127; kt = r >> 7;
        } else {
            int b2 = b - 32768;
            W = W2; oh = g_w2; KD = H_DIM; ND = D_DIM;
            e = b2 >> 12; int r = b2 & 4095; nt = r & 31; kt = r >> 5;
        }
        int n0 = nt * 32, k0 = kt * 32;
        int tx = tid & 31, ty = tid >> 5;
        const float* We = W + (size_t)e * KD * ND;
#pragma unroll
        for (int i = 0; i < 32; i += 8)
            ts[ty + i][tx] = We[(size_t)(k0 + ty + i) * ND + n0 + tx];
        __syncthreads();
        __half* ohe = oh + (size_t)e * KD * ND;
#pragma unroll
        for (int i = 0; i < 32; i += 8) {
            float v = ts[tx][ty + i];
            ohe[(size_t)(n0 + ty + i) * KD + (k0 + tx)] = __float2half_rn(v);
        }
        return;
    }
    if (b < R_BASE) {
        // ---- zero output ----
        int i = (b - Z_BASE) * 256 + tid;
        reinterpret_cast<float4*>(out)[i] = make_float4(0.f, 0.f, 0.f, 0.f);
        return;
    }
    if (b < TI_BASE) {
        // ---- router (+ fused x -> fp16); one warp/token, block-agg counts --
        if (tid < E_EXP) s_cnt[tid] = 0;
        __syncthreads();

        int t    = (b - R_BASE) * 8 + (tid >> 5);
        int lane = tid & 31;
        const float* xr = x + (size_t)t * D_DIM;

        float acc[E_EXP];
#pragma unroll
        for (int e = 0; e < E_EXP; e++) acc[e] = 0.f;
        for (int d = lane * 2; d < D_DIM; d += 64) {
            float2 xv2 = *(const float2*)(xr + d);
            __half2 hp = __floats2half2_rn(xv2.x, xv2.y);
            *(uint32_t*)(g_x16 + (size_t)t * D_DIM + d) = *(uint32_t*)&hp;

            const float4* w0 = reinterpret_cast<const float4*>(Wg + (size_t)d * E_EXP);
            const float4* w1 = reinterpret_cast<const float4*>(Wg + (size_t)(d + 1) * E_EXP);
            float4 wa = w0[0], wb = w0[1], wc = w1[0], wd = w1[1];
            acc[0] = fmaf(xv2.x, wa.x, fmaf(xv2.y, wc.x, acc[0]));
            acc[1] = fmaf(xv2.x, wa.y, fmaf(xv2.y, wc.y, acc[1]));
            acc[2] = fmaf(xv2.x, wa.z, fmaf(xv2.y, wc.z, acc[2]));
            acc[3] = fmaf(xv2.x, wa.w, fmaf(xv2.y, wc.w, acc[3]));
            acc[4] = fmaf(xv2.x, wb.x, fmaf(xv2.y, wd.x, acc[4]));
            acc[5] = fmaf(xv2.x, wb.y, fmaf(xv2.y, wd.y, acc[5]));
            acc[6] = fmaf(xv2.x, wb.z, fmaf(xv2.y, wd.z, acc[6]));
            acc[7] = fmaf(xv2.x, wb.w, fmaf(xv2.y, wd.w, acc[7]));
        }
#pragma unroll
        for (int e = 0; e < E_EXP; e++)
#pragma unroll
            for (int off = 16; off; off >>= 1)
                acc[e] += __shfl_xor_sync(0xffffffffu, acc[e], off);

        if (lane == 0) {
            float l[E_EXP];
#pragma unroll
            for (int e = 0; e < E_EXP; e++) l[e] = acc[e] + bg[e];
            float m = l[0];
#pragma unroll
            for (int e = 1; e < E_EXP; e++) m = fmaxf(m, l[e]);
            float s = 0.f;
#pragma unroll
            for (int e = 0; e < E_EXP; e++) { l[e] = expf(l[e] - m); s += l[e]; }
            float inv = 1.f / s;
            int i0 = 0;
#pragma unroll
            for (int e = 1; e < E_EXP; e++) if (l[e] > l[i0]) i0 = e;
            int i1 = (i0 == 0) ? 1 : 0;
#pragma unroll
            for (int e = 0; e < E_EXP; e++)
                if (e != i0 && l[e] > l[i1]) i1 = e;
            g_topi[2 * t + 0] = i0;  g_topw[2 * t + 0] = l[i0] * inv;
            g_topi[2 * t + 1] = i1;  g_topw[2 * t + 1] = l[i1] * inv;
            atomicAdd(&s_cnt[i0], 1);          // shared-mem aggregation
            atomicAdd(&s_cnt[i1], 1);
        }
        __syncthreads();
        if (tid < E_EXP && s_cnt[tid])
            atomicAdd(&g_counts[tid], s_cnt[tid]);
        return;
    }
    // ---- g_tok init ----
    {
        int i = (b - TI_BASE) * 256 + tid;
        if (i < MAX_SLOTS) g_tok[i] = -1;
    }
}

// ---------------- scatter (scan merged; warp-aggregated atomics) ------------
__global__ void scatter_kernel() {
    __shared__ int offp[E_EXP + 1];
    if (threadIdx.x == 0) {
        int o = 0;
        for (int e = 0; e < E_EXP; e++) {
            offp[e] = o;
            o += ((g_counts[e] + BM - 1) / BM) * BM;
        }
        offp[E_EXP] = o;
    }
    __syncthreads();

    if (blockIdx.x == 0) {
        for (int m = threadIdx.x; m < MAX_TILES; m += blockDim.x) {
            int s = m * BM, e = -1;
            for (int i = 0; i < E_EXP; i++)
                if (s >= offp[i] && s < offp[i + 1]) e = i;
            g_tile_expert[m] = e;
        }
    }

    int t    = blockIdx.x * blockDim.x + threadIdx.x;
    int lane = threadIdx.x & 31;
#pragma unroll
    for (int k = 0; k < 2; k++) {
        int e = g_topi[2 * t + k];
        unsigned mask  = __match_any_sync(0xffffffffu, e);
        int leader     = __ffs(mask) - 1;
        int base = 0;
        if (lane == leader) base = atomicAdd(&g_cursor[e], __popc(mask));
        base = __shfl_sync(0xffffffffu, base, leader);
        int rank = __popc(mask & ((1u << lane) - 1));
        int slot = offp[e] + base + rank;
        g_tok[slot]   = t;
        g_wslot[slot] = g_topw[2 * t + k];
    }
}

// ---------------- HMMA GEMM (single fp16, k-chunk 64) ----------------------
// PHASE 1: h = gelu( gather(x16) @ W1[e]^T + b1 ) -> g_h16  (+ counter reset)
// PHASE 2: out[tok] += w * ( h16 @ W2[e]^T + b2 )   (fused combine, RED.F32)
template <int PHASE>
__global__ void __launch_bounds__(256, 2) gemm_mma(const float* __restrict__ bias,
                                                   float* __restrict__ out) {
    constexpr int K  = (PHASE == 1) ? D_DIM : H_DIM;
    constexpr int N  = (PHASE == 1) ? H_DIM : D_DIM;
    constexpr int NC = K / 64;

    // reset routing counters for the next graph replay (dead after scatter)
    if (PHASE == 1 && blockIdx.x == 0 && blockIdx.y == 0 && threadIdx.x < E_EXP) {
        g_counts[threadIdx.x] = 0;
        g_cursor[threadIdx.x] = 0;
    }

    int mt_blk = blockIdx.y;
    int e = g_tile_expert[mt_blk];
    if (e < 0) return;
    int m0 = mt_blk * BM, n0 = blockIdx.x * 128;

    extern __shared__ char dyn_smem[];
    char* sm = (char*)(((uintptr_t)dyn_smem + 127) & ~(uintptr_t)127);
    uint32_t sb = s2u(sm);

    int tid  = threadIdx.x;
    int lane = tid & 31, wid = tid >> 5;
    int wm = wid >> 1, wn = wid & 1;

    float* bias_s = (float*)(sm + OFF_BIAS);
    int*   tok_s  = (int*)(sm + OFF_TOK);
    int*   ot_s   = (int*)(sm + OFF_OT);
    float* w_s    = (float*)(sm + OFF_W);

    if (tid < 128) {
        bias_s[tid] = bias[(size_t)e * N + n0 + tid];
        if (PHASE == 1) {
            int tk = g_tok[m0 + tid];
            tok_s[tid] = (tk < 0) ? 0 : tk;
        } else {
            tok_s[tid] = m0 + tid;
            ot_s[tid]  = g_tok[m0 + tid];          // may be -1 (padding)
            w_s[tid]   = g_wslot[m0 + tid];
        }
    }
    __syncthreads();

    const __half* A_g = (PHASE == 1) ? g_x16 : g_h16;
    const __half* B_g = ((PHASE == 1) ? g_w1 : g_w2) + ((size_t)e * N + n0) * K;

    // ldmatrix lane rows (128B rows, chunk ^ (row&7) swizzle)
    int q = lane >> 3, r = lane & 7;
    int rowA_[2], rowB_[4];
#pragma unroll
    for (int mt = 0; mt < 2; mt++)
        rowA_[mt] = wm * 32 + mt * 16 + (q & 1) * 8 + r;
#pragma unroll
    for (int j = 0; j < 4; j++)
        rowB_[j] = wn * 64 + j * 16 + (q >> 1) * 8 + r;
    int qhA = q >> 1;
    int qhB = q & 1;

    float acc[2][8][4];
#pragma unroll
    for (int a = 0; a < 2; a++)
#pragma unroll
        for (int b = 0; b < 8; b++)
#pragma unroll
            for (int c = 0; c < 4; c++) acc[a][b][c] = 0.f;

    auto load_stage = [&](int c) {
        if (c < NC) {
            int k0 = c * 64;
            uint32_t sbs = sb + (uint32_t)(c % 3) * STAGE_B;
#pragma unroll
            for (int i = 0; i < 4; i++) {
                int t = tid + i * 256;
                int row = t >> 3, chunk = t & 7;
                uint32_t soff = (uint32_t)row * 128 +
                                (((uint32_t)(chunk ^ (row & 7))) << 4);
                int kk = k0 + chunk * 8;
                cpa16(sbs + OFF_A + soff, A_g + (size_t)tok_s[row] * K + kk);
                cpa16(sbs + OFF_B + soff, B_g + (size_t)row * K + kk);
            }
        }
        CP_COMMIT();
    };

    load_stage(0);
    load_stage(1);

    for (int c = 0; c < NC; ++c) {
        CP_WAITG(1);
        __syncthreads();
        load_stage(c + 2);
        uint32_t sbs = sb + (uint32_t)(c % 3) * STAGE_B;
#pragma unroll
        for (int slice = 0; slice < 4; slice++) {
            uint32_t ah[2][4];
#pragma unroll
            for (int mt = 0; mt < 2; mt++) {
                int row = rowA_[mt];
                uint32_t off = (uint32_t)row * 128 +
                    (((uint32_t)((slice * 2 + qhA) ^ (row & 7))) << 4);
                LDSM4(ah[mt][0], ah[mt][1], ah[mt][2], ah[mt][3],
                      sbs + OFF_A + off);
            }
#pragma unroll
            for (int j = 0; j < 4; j++) {
                int row = rowB_[j];
                uint32_t off = (uint32_t)row * 128 +
                    (((uint32_t)((slice * 2 + qhB) ^ (row & 7))) << 4);
                uint32_t bh[4];
                LDSM4(bh[0], bh[1], bh[2], bh[3], sbs + OFF_B + off);
#pragma unroll
                for (int mt = 0; mt < 2; mt++) {
#pragma unroll
                    for (int jj = 0; jj < 2; jj++)
                        mma16816(acc[mt][j * 2 + jj], ah[mt], bh + jj * 2);
                }
            }
        }
    }

    // ---------------- epilogue ----------------
    int g = lane >> 2, tc = lane & 3;
#pragma unroll
    for (int mt = 0; mt < 2; mt++) {
        int rowl = wm * 32 + mt * 16 + g;
#pragma unroll
        for (int h = 0; h < 2; h++) {
            int rl = rowl + h * 8;
            if (PHASE == 1) {
                size_t base = (size_t)(m0 + rl) * N + n0 + wn * 64 + tc * 2;
#pragma unroll
                for (int nt = 0; nt < 8; nt++) {
                    int nb = wn * 64 + nt * 8 + tc * 2;
                    float u0 = acc[mt][nt][h * 2 + 0] + bias_s[nb];
                    float u1 = acc[mt][nt][h * 2 + 1] + bias_s[nb + 1];
                    u0 = 0.5f * u0 * (1.0f + erff(u0 * 0.7071067811865476f));
                    u1 = 0.5f * u1 * (1.0f + erff(u1 * 0.7071067811865476f));
                    __half2 p = __floats2half2_rn(u0, u1);
                    *(uint32_t*)(g_h16 + base + nt * 8) = *(uint32_t*)&p;
                }
            } else {
                int   ot = ot_s[rl];
                float w  = w_s[rl];
                if (ot >= 0) {
                    float* orow = out + (size_t)ot * D_DIM + n0 + wn * 64 + tc * 2;
#pragma unroll
                    for (int nt = 0; nt < 8; nt++) {
                        int nb = wn * 64 + nt * 8 + tc * 2;
                        float u0 = acc[mt][nt][h * 2 + 0] + bias_s[nb];
                        float u1 = acc[mt][nt][h * 2 + 1] + bias_s[nb + 1];
                        atomicAdd(orow + nt * 8 + 0, w * u0);
                        atomicAdd(orow + nt * 8 + 1, w * u1);
                    }
                }
            }
        }
    }
}

// ---------------- launch (single stream; graph-capture safe) ----------------
extern "C" void kernel_launch(void* const* d_in, const int* in_sizes, int n_in,
                              void* d_out, int out_size) {
    const float* x  = (const float*)d_in[0];
    const float* Wg = (const float*)d_in[1];
    const float* bg = (const float*)d_in[2];
    const float* W1 = (const float*)d_in[3];
    const float* b1 = (const float*)d_in[4];
    const float* W2 = (const float*)d_in[5];
    const float* b2 = (const float*)d_in[6];
    float* out = (float*)d_out;

    cudaFuncSetAttribute(gemm_mma<1>, cudaFuncAttributeMaxDynamicSharedMemorySize, SMEM_REQ);
    cudaFuncSetAttribute(gemm_mma<2>, cudaFuncAttributeMaxDynamicSharedMemorySize, SMEM_REQ);

    fused_prep_kernel<<<PREP_GRID, 256>>>(x, Wg, bg, W1, W2, out);
    scatter_kernel<<<T_TOK / 256, 256>>>();
    gemm_mma<1><<<dim3(H_DIM / 128, MAX_TILES), 256, SMEM_REQ>>>(b1, out);
    gemm_mma<2><<<dim3(D_DIM / 128, MAX_TILES), 256, SMEM_REQ>>>(b2, out);
}